// round 5
// baseline (speedup 1.0000x reference)
#include <cuda_runtime.h>
#include <math.h>

// Problem shapes (fixed by the dataset)
#define HW_   (768 * 768)       // pixels
#define NQ_   (HW_ / 4)         // pixel float4 quads
#define S_    8192              // chamfer points per cloud
#define NG_   100000            // gradients / sdf
#define NEQ_  (NG_ / 4)         // eik quads
#define NP_   50000             // consistency points

// Fused-kernel geometry
#define NBLK  148               // one block per SM, single wave
#define NTH   1024
#define C_CH  120               // chamfer blocks (4 combos x 30)
#define NMEM  (NBLK - C_CH)     // 28 memory-task blocks
#define NSUB  30                // blocks per (dir,sblk) combo
#define SPT   4                 // sources per thread
#define SRCB  (NTH * SPT)       // 4096 sources per combo
#define DCH   32                // dest tile size
#define NCHK  (S_ / DCH)        // 256 dest tiles

// Scratch (device globals; written fully every launch, no init needed)
__device__ float  g_minpart[4][NSUB][SRCB];   // per-block partial mins
__device__ double g_part[NBLK][12];           // per-block term partials
__device__ unsigned long long g_sync[2];      // monotone sync counters (never reset)

typedef unsigned long long u64;

// ---------------------------------------------------------------------------
// f32x2 packed math (sm_103a)
// ---------------------------------------------------------------------------
#define FMA_F32X2(d, a, b, c) \
    asm("fma.rn.f32x2 %0, %1, %2, %3;" : "=l"(d) : "l"(a), "l"(b), "l"(c))
#define PACK_F32X2(out, lo, hi) \
    asm("mov.b64 %0, {%1, %2};" : "=l"(out) : "f"(lo), "f"(hi))
#define UNPACK_F32X2(lo, hi, in) \
    asm("mov.b64 {%0, %1}, %2;" : "=f"(lo), "=f"(hi) : "l"(in))

// ---------------------------------------------------------------------------
// Reductions
// ---------------------------------------------------------------------------
__device__ __forceinline__ float warpSum(float v) {
    #pragma unroll
    for (int o = 16; o > 0; o >>= 1) v += __shfl_down_sync(0xffffffffu, v, o);
    return v;
}
__device__ float blockSum(float v) {
    __shared__ float s[32];
    int lane = threadIdx.x & 31, wid = threadIdx.x >> 5;
    __syncthreads();
    v = warpSum(v);
    if (lane == 0) s[wid] = v;
    __syncthreads();
    v = (threadIdx.x < (NTH / 32)) ? s[threadIdx.x] : 0.0f;
    if (wid == 0) v = warpSum(v);
    return v;
}
__device__ __forceinline__ double dwarpSum(double v) {
    #pragma unroll
    for (int o = 16; o > 0; o >>= 1) v += __shfl_down_sync(0xffffffffu, v, o);
    return v;
}
__device__ double dblockSum(double v) {
    __shared__ double sd[32];
    int lane = threadIdx.x & 31, wid = threadIdx.x >> 5;
    __syncthreads();
    v = dwarpSum(v);
    if (lane == 0) sd[wid] = v;
    __syncthreads();
    v = (threadIdx.x < (NTH / 32)) ? sd[threadIdx.x] : 0.0;
    if (wid == 0) v = dwarpSum(v);
    return v;
}

// ---------------------------------------------------------------------------
// Grid-wide sync. Counter is never reset; each launch adds exactly NBLK per
// counter, so "count % NBLK == 0" <=> all blocks of THIS launch arrived.
// ---------------------------------------------------------------------------
__device__ __forceinline__ void gridSync(int s) {
    __syncthreads();
    if (threadIdx.x == 0) {
        __threadfence();
        atomicAdd(&g_sync[s], 1ULL);
        while ((*(volatile unsigned long long*)&g_sync[s]) % NBLK != 0ULL)
            __nanosleep(64);
        __threadfence();
    }
    __syncthreads();
}

// ---------------------------------------------------------------------------
// The fused kernel
// ---------------------------------------------------------------------------
__global__ void __launch_bounds__(NTH, 1)
k_fused(const float* __restrict__ npred, const float* __restrict__ ngt,
        const float* __restrict__ dpred, const float* __restrict__ dgt,
        const float* __restrict__ X,     const float* __restrict__ Y,
        const float* __restrict__ mask,  const float* __restrict__ comp,
        const float* __restrict__ grad,  const float* __restrict__ sdf,
        const float* __restrict__ nw,    const float* __restrict__ vis,
        const float* __restrict__ w,     float* __restrict__ out) {
    const int bid = blockIdx.x;
    const int t   = threadIdx.x;

    // ======================= PHASE 1 =======================
    if (bid < C_CH) {
        // ---------------- chamfer role ----------------
        __shared__ __align__(16) float sy0[2][DCH];
        __shared__ __align__(16) float sy1[2][DCH];
        __shared__ __align__(16) float sy2[2][DCH];
        __shared__ __align__(16) float syy[2][DCH];

        const int combo = bid / NSUB;          // 0..3 = (dir, sblk)
        const int sub   = bid % NSUB;
        const int dir   = combo >> 1;
        const int sblk  = combo & 1;
        const float* src = dir ? Y : X;
        const float* dst = dir ? X : Y;

        // Load SPT sources per thread; pack coords as {x,x}
        u64 xp0[SPT], xp1[SPT], xp2[SPT];
        float xx[SPT], bl[SPT], bh[SPT];
        const int sbase = sblk * SRCB + t;
        #pragma unroll
        for (int s = 0; s < SPT; s++) {
            const int si = sbase + s * NTH;
            float a = __ldg(&src[3 * si + 0]);
            float b = __ldg(&src[3 * si + 1]);
            float c = __ldg(&src[3 * si + 2]);
            PACK_F32X2(xp0[s], a, a);
            PACK_F32X2(xp1[s], b, b);
            PACK_F32X2(xp2[s], c, c);
            xx[s] = fmaf(a, a, fmaf(b, b, c * c));
            bl[s] = 3.4e38f;  bh[s] = 3.4e38f;
        }

        // Sweep this block's dest tiles (chunk = sub, sub+NSUB, ...)
        float nx0 = 0.f, nx1 = 0.f, nx2 = 0.f;
        int chunk = sub;
        if (t < DCH) {
            const int p = chunk * DCH + t;
            nx0 = dst[3 * p + 0]; nx1 = dst[3 * p + 1]; nx2 = dst[3 * p + 2];
        }
        int buf = 0;
        while (chunk < NCHK) {
            __syncthreads();
            if (t < DCH) {
                sy0[buf][t] = -2.0f * nx0;
                sy1[buf][t] = -2.0f * nx1;
                sy2[buf][t] = -2.0f * nx2;
                syy[buf][t] = fmaf(nx0, nx0, fmaf(nx1, nx1, nx2 * nx2));
            }
            __syncthreads();
            const int nchunk = chunk + NSUB;
            if (nchunk < NCHK && t < DCH) {          // prefetch next tile
                const int p = nchunk * DCH + t;
                nx0 = dst[3 * p + 0]; nx1 = dst[3 * p + 1]; nx2 = dst[3 * p + 2];
            }
            const u64* p0 = (const u64*)sy0[buf];
            const u64* p1 = (const u64*)sy1[buf];
            const u64* p2 = (const u64*)sy2[buf];
            const u64* pw = (const u64*)syy[buf];
            #pragma unroll 4
            for (int j = 0; j < DCH / 2; j++) {
                const u64 a = p0[j], b = p1[j], c = p2[j], wv = pw[j];
                #pragma unroll
                for (int s = 0; s < SPT; s++) {
                    u64 acc;
                    FMA_F32X2(acc, xp0[s], a, wv);
                    FMA_F32X2(acc, xp1[s], b, acc);
                    FMA_F32X2(acc, xp2[s], c, acc);
                    float lo, hi;
                    UNPACK_F32X2(lo, hi, acc);
                    bl[s] = fminf(bl[s], lo);
                    bh[s] = fminf(bh[s], hi);
                }
            }
            buf ^= 1;
            chunk = nchunk;
        }
        // Write this block's partial mins (complete slice, no init needed)
        #pragma unroll
        for (int s = 0; s < SPT; s++)
            g_minpart[combo][sub][t + s * NTH] = xx[s] + fminf(bl[s], bh[s]);
    } else {
        // ---------------- memory role ----------------
        const int mb   = bid - C_CH;
        const int gtid = mb * NTH + t;
        const int MT   = NMEM * NTH;

        // pixel reductions
        float cnt = 0.f, nerr = 0.f, den = 0.f, num = 0.f, bce = 0.f;
        const float4* m4p = (const float4*)mask;
        const float4* c4p = (const float4*)comp;
        const float4* g4p = (const float4*)dgt;
        const float4* p4p = (const float4*)dpred;
        const float4* np4 = (const float4*)npred;
        const float4* ng4 = (const float4*)ngt;
        for (int q = gtid; q < NQ_; q += MT) {
            float4 m4 = m4p[q], c4 = c4p[q], g4 = g4p[q], p4 = p4p[q];
            float4 a0 = np4[3 * q + 0], a1 = np4[3 * q + 1], a2 = np4[3 * q + 2];
            float4 b0 = ng4[3 * q + 0], b1 = ng4[3 * q + 1], b2 = ng4[3 * q + 2];
            float m[4] = { m4.x > 0.5f ? 1.f : 0.f, m4.y > 0.5f ? 1.f : 0.f,
                           m4.z > 0.5f ? 1.f : 0.f, m4.w > 0.5f ? 1.f : 0.f };
            float cc[4] = { c4.x, c4.y, c4.z, c4.w };
            float gg[4] = { g4.x, g4.y, g4.z, g4.w };
            float pp[4] = { p4.x, p4.y, p4.z, p4.w };
            float e[4];
            { float d0=a0.x-b0.x, d1=a0.y-b0.y, d2=a0.z-b0.z; e[0]=fmaf(d0,d0,fmaf(d1,d1,d2*d2)); }
            { float d0=a0.w-b0.w, d1=a1.x-b1.x, d2=a1.y-b1.y; e[1]=fmaf(d0,d0,fmaf(d1,d1,d2*d2)); }
            { float d0=a1.z-b1.z, d1=a1.w-b1.w, d2=a2.x-b2.x; e[2]=fmaf(d0,d0,fmaf(d1,d1,d2*d2)); }
            { float d0=a2.y-b2.y, d1=a2.z-b2.z, d2=a2.w-b2.w; e[3]=fmaf(d0,d0,fmaf(d1,d1,d2*d2)); }
            #pragma unroll
            for (int k = 0; k < 4; k++) {
                cnt  += m[k];
                nerr += m[k] * e[k];
                float vg = m[k] * gg[k], vp = m[k] * pp[k];
                den = fmaf(vg, vg, den);
                num = fmaf(vg, vp, num);
                float c = fminf(fmaxf(cc[k], 1e-5f), 1.0f - 1e-5f);
                bce += m[k] * __logf(c) + (1.0f - m[k]) * __logf(1.0f - c);
            }
        }

        // eikonal + sdf
        float eik = 0.f, sda = 0.f;
        const float4* gr4 = (const float4*)grad;
        const float4* sd4 = (const float4*)sdf;
        for (int q = gtid; q < NEQ_; q += MT) {
            float4 g0 = gr4[3 * q + 0], g1 = gr4[3 * q + 1], g2 = gr4[3 * q + 2];
            float4 s4 = sd4[q];
            float n;
            n = sqrtf(fmaf(g0.x,g0.x,fmaf(g0.y,g0.y,g0.z*g0.z))) - 1.f; eik = fmaf(n,n,eik);
            n = sqrtf(fmaf(g0.w,g0.w,fmaf(g1.x,g1.x,g1.y*g1.y))) - 1.f; eik = fmaf(n,n,eik);
            n = sqrtf(fmaf(g1.z,g1.z,fmaf(g1.w,g1.w,g2.x*g2.x))) - 1.f; eik = fmaf(n,n,eik);
            n = sqrtf(fmaf(g2.y,g2.y,fmaf(g2.z,g2.z,g2.w*g2.w))) - 1.f; eik = fmaf(n,n,eik);
            sda += fabsf(s4.x) + fabsf(s4.y) + fabsf(s4.z) + fabsf(s4.w);
        }

        // consistency
        float con = 0.f, tot = 0.f;
        const float4* nw4  = (const float4*)nw;
        const float4* vs4  = (const float4*)vis;
        for (int p = gtid; p < NP_; p += MT) {
            float wt = w[p];
            float4 v  = vs4[p];
            float4 n0 = nw4[3 * p + 0], n1 = nw4[3 * p + 1], n2 = nw4[3 * p + 2];
            { float vp = v.x*v.y; tot += vp;
              float d0=n0.x-n0.w, d1=n0.y-n1.x, d2=n0.z-n1.y;
              con = fmaf(fmaf(d0,d0,fmaf(d1,d1,d2*d2))*vp, wt, con); }
            { float vp = v.y*v.z; tot += vp;
              float d0=n0.w-n1.z, d1=n1.x-n1.w, d2=n1.y-n2.x;
              con = fmaf(fmaf(d0,d0,fmaf(d1,d1,d2*d2))*vp, wt, con); }
            { float vp = v.z*v.w; tot += vp;
              float d0=n1.z-n2.y, d1=n1.w-n2.z, d2=n2.x-n2.w;
              con = fmaf(fmaf(d0,d0,fmaf(d1,d1,d2*d2))*vp, wt, con); }
        }

        float r;
        r = blockSum(cnt);  if (t == 0) g_part[bid][0] = (double)r;
        r = blockSum(nerr); if (t == 0) g_part[bid][1] = (double)r;
        r = blockSum(den);  if (t == 0) g_part[bid][2] = (double)r;
        r = blockSum(num);  if (t == 0) g_part[bid][3] = (double)r;
        r = blockSum(bce);  if (t == 0) g_part[bid][4] = (double)r;
        r = blockSum(eik);  if (t == 0) g_part[bid][5] = (double)r;
        r = blockSum(sda);  if (t == 0) g_part[bid][6] = (double)r;
        r = blockSum(con);  if (t == 0) g_part[bid][7] = (double)r;
        r = blockSum(tot);  if (t == 0) g_part[bid][8] = (double)r;
    }

    // ======================= SYNC A =======================
    gridSync(0);

    // ======================= PHASE 2 =======================
    // depth second pass (needs scale from phase-1 den/num partials)
    {
        double dden = 0.0, dnum = 0.0;
        #pragma unroll
        for (int i = 0; i < NMEM; i++) {
            dden += g_part[C_CH + i][2];
            dnum += g_part[C_CH + i][3];
        }
        float scale = (float)(dnum / dden);
        if (!isfinite(scale)) scale = 1.0f;

        float ds = 0.f;
        const float4* m4p = (const float4*)mask;
        const float4* g4p = (const float4*)dgt;
        const float4* p4p = (const float4*)dpred;
        for (int q = bid * NTH + t; q < NQ_; q += NBLK * NTH) {
            float4 m4 = m4p[q], g4 = g4p[q], p4 = p4p[q];
            float m;
            m = m4.x > 0.5f ? 1.f : 0.f; ds += fabsf(fmaf(m*g4.x, scale, -(m*p4.x)));
            m = m4.y > 0.5f ? 1.f : 0.f; ds += fabsf(fmaf(m*g4.y, scale, -(m*p4.y)));
            m = m4.z > 0.5f ? 1.f : 0.f; ds += fabsf(fmaf(m*g4.z, scale, -(m*p4.z)));
            m = m4.w > 0.5f ? 1.f : 0.f; ds += fabsf(fmaf(m*g4.w, scale, -(m*p4.w)));
        }
        float r = blockSum(ds);
        if (t == 0) g_part[bid][9] = (double)r;
    }
    // chamfer: min over the NSUB sub-block partials, then sqrt
    {
        float ss = 0.f;
        for (int s = bid * NTH + t; s < 4 * SRCB; s += NBLK * NTH) {
            const int combo = s >> 12;          // / SRCB (4096)
            const int idx   = s & (SRCB - 1);
            float mn = 3.4e38f;
            #pragma unroll
            for (int sub = 0; sub < NSUB; sub++)
                mn = fminf(mn, g_minpart[combo][sub][idx]);
            ss += sqrtf(fmaxf(mn, 0.0f));
        }
        float r = blockSum(ss);
        if (t == 0) g_part[bid][10] = (double)r;
    }

    // ======================= SYNC B =======================
    gridSync(1);

    // ======================= FINAL (block 0) =======================
    if (bid == 0) {
        double sum[11];
        #pragma unroll
        for (int term = 0; term < 9; term++) {
            double v = (t < NMEM) ? g_part[C_CH + t][term] : 0.0;
            sum[term] = dblockSum(v);
        }
        { double v = (t < NBLK) ? g_part[t][9]  : 0.0; sum[9]  = dblockSum(v); }
        { double v = (t < NBLK) ? g_part[t][10] : 0.0; sum[10] = dblockSum(v); }

        if (t == 0) {
            double mask_sum = sum[0] + 1e-5;
            double normal_loss = sum[1] / mask_sum;

            double den = sum[2];
            double depth_loss = sum[9] / (mask_sum + 1e-8);
            if (den < 1e-10) depth_loss = 0.0;
            if (!isfinite(depth_loss)) depth_loss = 0.0;

            double pc_loss   = sum[10] / (double)S_;
            double mask_loss = -sum[4] / (double)HW_;
            double eik_loss  = sum[5] / (double)NG_;
            double sdf_loss  = sum[6] / (double)NG_;
            double con_loss  = (sum[8] > 0.0) ? (sum[7] / sum[8]) : 0.0;

            out[0] = (float)(normal_loss + depth_loss + pc_loss + mask_loss +
                             eik_loss + sdf_loss + con_loss);
        }
    }
}

// ---------------------------------------------------------------------------
// Launch
// ---------------------------------------------------------------------------
extern "C" void kernel_launch(void* const* d_in, const int* in_sizes, int n_in,
                              void* d_out, int out_size) {
    const float* normal_pred = (const float*)d_in[0];
    const float* normal_gt   = (const float*)d_in[1];
    const float* depth_pred  = (const float*)d_in[2];
    const float* depth_gt    = (const float*)d_in[3];
    const float* X           = (const float*)d_in[4];
    const float* Y           = (const float*)d_in[5];
    const float* mask        = (const float*)d_in[6];
    const float* comp_mask   = (const float*)d_in[7];
    const float* gradients   = (const float*)d_in[8];
    const float* sdf         = (const float*)d_in[9];
    const float* nw_all      = (const float*)d_in[10];
    const float* vis_mask    = (const float*)d_in[11];
    const float* weights     = (const float*)d_in[12];
    float* out = (float*)d_out;

    k_fused<<<NBLK, NTH>>>(normal_pred, normal_gt, depth_pred, depth_gt,
                           X, Y, mask, comp_mask, gradients, sdf,
                           nw_all, vis_mask, weights, out);
}

// round 6
// speedup vs baseline: 1.4481x; 1.4481x over previous
#include <cuda_runtime.h>
#include <math.h>

// Problem shapes (fixed by the dataset)
#define HW_   (768 * 768)       // pixels
#define NQ_   (HW_ / 4)         // pixel float4 quads
#define S_    8192              // chamfer points per cloud
#define NG_   100000            // gradients / sdf
#define NEQ_  (NG_ / 4)         // eik quads
#define NP_   50000             // consistency points

// Fused-kernel geometry
#define NBLK  148               // one block per SM, single wave
#define NTH   512
#define C_CH  128               // chamfer blocks (2 source-halves x 64 dest-strides)
#define NMEM  (NBLK - C_CH)     // 20 memory-task blocks
#define NSUB  64                // dest-stride blocks per source-half
#define SPT   8                 // sources per thread
#define SRCB  (NTH * SPT)       // 4096 sources per half
#define DCH   32                // dest tile size
#define NCHK  (S_ / DCH)        // 256 dest tiles (4 per chamfer block)

// Scratch (device globals; fully written every launch, no init needed)
__device__ float  g_minpart[2][NSUB][SRCB];   // row-min partials (X->Y dir)
__device__ float  g_colmin[2][S_];            // col-min partials (Y->X dir), per source-half
__device__ double g_part[NBLK][12];           // per-block term partials
__device__ unsigned long long g_sync[2];      // monotone sync counters (never reset)

typedef unsigned long long u64;

// ---------------------------------------------------------------------------
// f32x2 packed math (sm_103a)
// ---------------------------------------------------------------------------
#define FMA_F32X2(d, a, b, c) \
    asm("fma.rn.f32x2 %0, %1, %2, %3;" : "=l"(d) : "l"(a), "l"(b), "l"(c))
#define ADD_F32X2(d, a, b) \
    asm("add.rn.f32x2 %0, %1, %2;" : "=l"(d) : "l"(a), "l"(b))
#define PACK_F32X2(out, lo, hi) \
    asm("mov.b64 %0, {%1, %2};" : "=l"(out) : "f"(lo), "f"(hi))
#define UNPACK_F32X2(lo, hi, in) \
    asm("mov.b64 {%0, %1}, %2;" : "=f"(lo), "=f"(hi) : "l"(in))

// ---------------------------------------------------------------------------
// Reductions
// ---------------------------------------------------------------------------
__device__ __forceinline__ float warpSum(float v) {
    #pragma unroll
    for (int o = 16; o > 0; o >>= 1) v += __shfl_down_sync(0xffffffffu, v, o);
    return v;
}
__device__ float blockSum(float v) {
    __shared__ float s[32];
    int lane = threadIdx.x & 31, wid = threadIdx.x >> 5;
    __syncthreads();
    v = warpSum(v);
    if (lane == 0) s[wid] = v;
    __syncthreads();
    v = (threadIdx.x < (NTH / 32)) ? s[threadIdx.x] : 0.0f;
    if (wid == 0) v = warpSum(v);
    return v;
}
__device__ __forceinline__ double dwarpSum(double v) {
    #pragma unroll
    for (int o = 16; o > 0; o >>= 1) v += __shfl_down_sync(0xffffffffu, v, o);
    return v;
}
__device__ double dblockSum(double v) {
    __shared__ double sd[32];
    int lane = threadIdx.x & 31, wid = threadIdx.x >> 5;
    __syncthreads();
    v = dwarpSum(v);
    if (lane == 0) sd[wid] = v;
    __syncthreads();
    v = (threadIdx.x < (NTH / 32)) ? sd[threadIdx.x] : 0.0;
    if (wid == 0) v = dwarpSum(v);
    return v;
}

// ---------------------------------------------------------------------------
// Grid-wide sync. Counter is never reset; each launch adds exactly NBLK per
// counter, so "count % NBLK == 0" <=> all blocks of THIS launch arrived.
// ---------------------------------------------------------------------------
__device__ __forceinline__ void gridSync(int s) {
    __syncthreads();
    if (threadIdx.x == 0) {
        __threadfence();
        atomicAdd(&g_sync[s], 1ULL);
        while ((*(volatile unsigned long long*)&g_sync[s]) % NBLK != 0ULL)
            __nanosleep(64);
        __threadfence();
    }
    __syncthreads();
}

// ---------------------------------------------------------------------------
// The fused kernel
// ---------------------------------------------------------------------------
__global__ void __launch_bounds__(NTH, 1)
k_fused(const float* __restrict__ npred, const float* __restrict__ ngt,
        const float* __restrict__ dpred, const float* __restrict__ dgt,
        const float* __restrict__ X,     const float* __restrict__ Y,
        const float* __restrict__ mask,  const float* __restrict__ comp,
        const float* __restrict__ grad,  const float* __restrict__ sdf,
        const float* __restrict__ nw,    const float* __restrict__ vis,
        const float* __restrict__ w,     float* __restrict__ out) {
    const int bid  = blockIdx.x;
    const int t    = threadIdx.x;
    const int lane = t & 31;
    const int wid  = t >> 5;

    // ======================= PHASE 1 =======================
    if (bid < C_CH) {
        // ------- chamfer role: both directions from one pass over pairs -----
        __shared__ __align__(16) float sy0[DCH];
        __shared__ __align__(16) float sy1[DCH];
        __shared__ __align__(16) float sy2[DCH];
        __shared__ __align__(16) float syy[DCH];
        __shared__ float scm[NTH / 32][DCH];   // per-warp column-min partials

        const int sblk = bid / NSUB;           // source half 0/1
        const int sub  = bid % NSUB;           // dest-tile stride offset
        const float* src = X;                  // rows: X -> Y
        const float* dst = Y;                  // cols: Y -> X

        // Load SPT sources per thread; pack coords as {v,v}, xx as {xx,xx}
        u64 xp0[SPT], xp1[SPT], xp2[SPT], xxp[SPT];
        float bl[SPT], bh[SPT];
        const int sbase = sblk * SRCB + t;
        #pragma unroll
        for (int s = 0; s < SPT; s++) {
            const int si = sbase + s * NTH;
            float a = __ldg(&src[3 * si + 0]);
            float b = __ldg(&src[3 * si + 1]);
            float c = __ldg(&src[3 * si + 2]);
            PACK_F32X2(xp0[s], a, a);
            PACK_F32X2(xp1[s], b, b);
            PACK_F32X2(xp2[s], c, c);
            float xs = fmaf(a, a, fmaf(b, b, c * c));
            PACK_F32X2(xxp[s], xs, xs);
            bl[s] = 3.4e38f;  bh[s] = 3.4e38f;
        }

        // Prefetch first dest tile into registers
        float nx0 = 0.f, nx1 = 0.f, nx2 = 0.f;
        if (t < DCH) {
            const int p = sub * DCH + t;
            nx0 = dst[3 * p + 0]; nx1 = dst[3 * p + 1]; nx2 = dst[3 * p + 2];
        }

        for (int chunk = sub; chunk < NCHK; chunk += NSUB) {
            __syncthreads();                    // smem free (prev tile done)
            if (t < DCH) {
                sy0[t] = -2.0f * nx0;
                sy1[t] = -2.0f * nx1;
                sy2[t] = -2.0f * nx2;
                syy[t] = fmaf(nx0, nx0, fmaf(nx1, nx1, nx2 * nx2));
            }
            __syncthreads();
            const int nchunk = chunk + NSUB;
            if (nchunk < NCHK && t < DCH) {     // prefetch next tile
                const int p = nchunk * DCH + t;
                nx0 = dst[3 * p + 0]; nx1 = dst[3 * p + 1]; nx2 = dst[3 * p + 2];
            }

            const u64* p0 = (const u64*)sy0;
            const u64* p1 = (const u64*)sy1;
            const u64* p2 = (const u64*)sy2;
            const u64* pw = (const u64*)syy;

            u64 ca = p0[0], cb = p1[0], cc = p2[0], cw = pw[0];
            #pragma unroll
            for (int j = 0; j < DCH / 2; j++) {
                const u64 a = ca, b = cb, c = cc, wv = cw;
                if (j + 1 < DCH / 2) {          // register prefetch next pair
                    ca = p0[j + 1]; cb = p1[j + 1];
                    cc = p2[j + 1]; cw = pw[j + 1];
                }
                float cl = 3.4e38f, ch = 3.4e38f;   // column mins (2 dests)
                #pragma unroll
                for (int s = 0; s < SPT; s++) {
                    u64 acc;
                    FMA_F32X2(acc, xp0[s], a, wv);
                    FMA_F32X2(acc, xp1[s], b, acc);
                    FMA_F32X2(acc, xp2[s], c, acc);
                    float lo, hi;
                    UNPACK_F32X2(lo, hi, acc);
                    bl[s] = fminf(bl[s], lo);       // row min (xx deferred)
                    bh[s] = fminf(bh[s], hi);
                    u64 tc;
                    ADD_F32X2(tc, acc, xxp[s]);     // full d^2 for column min
                    float tl, th;
                    UNPACK_F32X2(tl, th, tc);
                    cl = fminf(cl, tl);
                    ch = fminf(ch, th);
                }
                // warp-reduce column mins
                #pragma unroll
                for (int o = 16; o > 0; o >>= 1) {
                    cl = fminf(cl, __shfl_xor_sync(0xffffffffu, cl, o));
                    ch = fminf(ch, __shfl_xor_sync(0xffffffffu, ch, o));
                }
                if (lane == 0) {
                    scm[wid][2 * j]     = cl;
                    scm[wid][2 * j + 1] = ch;
                }
            }
            __syncthreads();
            if (t < DCH) {                      // combine 16 warps per column
                float mn = 3.4e38f;
                #pragma unroll
                for (int ww = 0; ww < NTH / 32; ww++)
                    mn = fminf(mn, scm[ww][t]);
                g_colmin[sblk][chunk * DCH + t] = mn;
            }
        }
        // Write row-min partials (complete slice, no init needed)
        #pragma unroll
        for (int s = 0; s < SPT; s++) {
            float xs, dummy;
            UNPACK_F32X2(xs, dummy, xxp[s]);
            g_minpart[sblk][sub][t + s * NTH] = xs + fminf(bl[s], bh[s]);
        }
    } else {
        // ---------------- memory role ----------------
        const int mb   = bid - C_CH;
        const int gtid = mb * NTH + t;
        const int MT   = NMEM * NTH;

        // pixel reductions
        float cnt = 0.f, nerr = 0.f, den = 0.f, num = 0.f, bce = 0.f;
        const float4* m4p = (const float4*)mask;
        const float4* c4p = (const float4*)comp;
        const float4* g4p = (const float4*)dgt;
        const float4* p4p = (const float4*)dpred;
        const float4* np4 = (const float4*)npred;
        const float4* ng4 = (const float4*)ngt;
        for (int q = gtid; q < NQ_; q += MT) {
            float4 m4 = m4p[q], c4 = c4p[q], g4 = g4p[q], p4 = p4p[q];
            float4 a0 = np4[3 * q + 0], a1 = np4[3 * q + 1], a2 = np4[3 * q + 2];
            float4 b0 = ng4[3 * q + 0], b1 = ng4[3 * q + 1], b2 = ng4[3 * q + 2];
            float m[4] = { m4.x > 0.5f ? 1.f : 0.f, m4.y > 0.5f ? 1.f : 0.f,
                           m4.z > 0.5f ? 1.f : 0.f, m4.w > 0.5f ? 1.f : 0.f };
            float cc[4] = { c4.x, c4.y, c4.z, c4.w };
            float gg[4] = { g4.x, g4.y, g4.z, g4.w };
            float pp[4] = { p4.x, p4.y, p4.z, p4.w };
            float e[4];
            { float d0=a0.x-b0.x, d1=a0.y-b0.y, d2=a0.z-b0.z; e[0]=fmaf(d0,d0,fmaf(d1,d1,d2*d2)); }
            { float d0=a0.w-b0.w, d1=a1.x-b1.x, d2=a1.y-b1.y; e[1]=fmaf(d0,d0,fmaf(d1,d1,d2*d2)); }
            { float d0=a1.z-b1.z, d1=a1.w-b1.w, d2=a2.x-b2.x; e[2]=fmaf(d0,d0,fmaf(d1,d1,d2*d2)); }
            { float d0=a2.y-b2.y, d1=a2.z-b2.z, d2=a2.w-b2.w; e[3]=fmaf(d0,d0,fmaf(d1,d1,d2*d2)); }
            #pragma unroll
            for (int k = 0; k < 4; k++) {
                cnt  += m[k];
                nerr += m[k] * e[k];
                float vg = m[k] * gg[k], vp = m[k] * pp[k];
                den = fmaf(vg, vg, den);
                num = fmaf(vg, vp, num);
                float c = fminf(fmaxf(cc[k], 1e-5f), 1.0f - 1e-5f);
                bce += m[k] * __logf(c) + (1.0f - m[k]) * __logf(1.0f - c);
            }
        }

        // eikonal + sdf
        float eik = 0.f, sda = 0.f;
        const float4* gr4 = (const float4*)grad;
        const float4* sd4 = (const float4*)sdf;
        for (int q = gtid; q < NEQ_; q += MT) {
            float4 g0 = gr4[3 * q + 0], g1 = gr4[3 * q + 1], g2 = gr4[3 * q + 2];
            float4 s4 = sd4[q];
            float n;
            n = sqrtf(fmaf(g0.x,g0.x,fmaf(g0.y,g0.y,g0.z*g0.z))) - 1.f; eik = fmaf(n,n,eik);
            n = sqrtf(fmaf(g0.w,g0.w,fmaf(g1.x,g1.x,g1.y*g1.y))) - 1.f; eik = fmaf(n,n,eik);
            n = sqrtf(fmaf(g1.z,g1.z,fmaf(g1.w,g1.w,g2.x*g2.x))) - 1.f; eik = fmaf(n,n,eik);
            n = sqrtf(fmaf(g2.y,g2.y,fmaf(g2.z,g2.z,g2.w*g2.w))) - 1.f; eik = fmaf(n,n,eik);
            sda += fabsf(s4.x) + fabsf(s4.y) + fabsf(s4.z) + fabsf(s4.w);
        }

        // consistency
        float con = 0.f, tot = 0.f;
        const float4* nw4  = (const float4*)nw;
        const float4* vs4  = (const float4*)vis;
        for (int p = gtid; p < NP_; p += MT) {
            float wt = w[p];
            float4 v  = vs4[p];
            float4 n0 = nw4[3 * p + 0], n1 = nw4[3 * p + 1], n2 = nw4[3 * p + 2];
            { float vp = v.x*v.y; tot += vp;
              float d0=n0.x-n0.w, d1=n0.y-n1.x, d2=n0.z-n1.y;
              con = fmaf(fmaf(d0,d0,fmaf(d1,d1,d2*d2))*vp, wt, con); }
            { float vp = v.y*v.z; tot += vp;
              float d0=n0.w-n1.z, d1=n1.x-n1.w, d2=n1.y-n2.x;
              con = fmaf(fmaf(d0,d0,fmaf(d1,d1,d2*d2))*vp, wt, con); }
            { float vp = v.z*v.w; tot += vp;
              float d0=n1.z-n2.y, d1=n1.w-n2.z, d2=n2.x-n2.w;
              con = fmaf(fmaf(d0,d0,fmaf(d1,d1,d2*d2))*vp, wt, con); }
        }

        float r;
        r = blockSum(cnt);  if (t == 0) g_part[bid][0] = (double)r;
        r = blockSum(nerr); if (t == 0) g_part[bid][1] = (double)r;
        r = blockSum(den);  if (t == 0) g_part[bid][2] = (double)r;
        r = blockSum(num);  if (t == 0) g_part[bid][3] = (double)r;
        r = blockSum(bce);  if (t == 0) g_part[bid][4] = (double)r;
        r = blockSum(eik);  if (t == 0) g_part[bid][5] = (double)r;
        r = blockSum(sda);  if (t == 0) g_part[bid][6] = (double)r;
        r = blockSum(con);  if (t == 0) g_part[bid][7] = (double)r;
        r = blockSum(tot);  if (t == 0) g_part[bid][8] = (double)r;
    }

    // ======================= SYNC A =======================
    gridSync(0);

    // ======================= PHASE 2 =======================
    // depth second pass (needs scale from phase-1 den/num partials)
    {
        double dden = 0.0, dnum = 0.0;
        #pragma unroll
        for (int i = 0; i < NMEM; i++) {
            dden += g_part[C_CH + i][2];
            dnum += g_part[C_CH + i][3];
        }
        float scale = (float)(dnum / dden);
        if (!isfinite(scale)) scale = 1.0f;

        float ds = 0.f;
        const float4* m4p = (const float4*)mask;
        const float4* g4p = (const float4*)dgt;
        const float4* p4p = (const float4*)dpred;
        for (int q = bid * NTH + t; q < NQ_; q += NBLK * NTH) {
            float4 m4 = m4p[q], g4 = g4p[q], p4 = p4p[q];
            float m;
            m = m4.x > 0.5f ? 1.f : 0.f; ds += fabsf(fmaf(m*g4.x, scale, -(m*p4.x)));
            m = m4.y > 0.5f ? 1.f : 0.f; ds += fabsf(fmaf(m*g4.y, scale, -(m*p4.y)));
            m = m4.z > 0.5f ? 1.f : 0.f; ds += fabsf(fmaf(m*g4.z, scale, -(m*p4.z)));
            m = m4.w > 0.5f ? 1.f : 0.f; ds += fabsf(fmaf(m*g4.w, scale, -(m*p4.w)));
        }
        float r = blockSum(ds);
        if (t == 0) g_part[bid][9] = (double)r;
    }
    // chamfer: row mins (min over NSUB dest-strides) + col mins (min over 2 halves)
    {
        float ss = 0.f;
        // rows: sources 0..2*SRCB-1
        for (int s = bid * NTH + t; s < 2 * SRCB; s += NBLK * NTH) {
            const int sb  = s >> 12;            // / SRCB (4096)
            const int idx = s & (SRCB - 1);
            float mn = 3.4e38f;
            #pragma unroll 8
            for (int sub = 0; sub < NSUB; sub++)
                mn = fminf(mn, g_minpart[sb][sub][idx]);
            ss += sqrtf(fmaxf(mn, 0.0f));
        }
        // cols: dests 0..S_-1
        for (int d = bid * NTH + t; d < S_; d += NBLK * NTH) {
            float mn = fminf(g_colmin[0][d], g_colmin[1][d]);
            ss += sqrtf(fmaxf(mn, 0.0f));
        }
        float r = blockSum(ss);
        if (t == 0) g_part[bid][10] = (double)r;
    }

    // ======================= SYNC B =======================
    gridSync(1);

    // ======================= FINAL (block 0) =======================
    if (bid == 0) {
        double sum[11];
        #pragma unroll
        for (int term = 0; term < 9; term++) {
            double v = (t < NMEM) ? g_part[C_CH + t][term] : 0.0;
            sum[term] = dblockSum(v);
        }
        { double v = (t < NBLK) ? g_part[t][9]  : 0.0; sum[9]  = dblockSum(v); }
        { double v = (t < NBLK) ? g_part[t][10] : 0.0; sum[10] = dblockSum(v); }

        if (t == 0) {
            double mask_sum = sum[0] + 1e-5;
            double normal_loss = sum[1] / mask_sum;

            double den = sum[2];
            double depth_loss = sum[9] / (mask_sum + 1e-8);
            if (den < 1e-10) depth_loss = 0.0;
            if (!isfinite(depth_loss)) depth_loss = 0.0;

            double pc_loss   = sum[10] / (double)S_;
            double mask_loss = -sum[4] / (double)HW_;
            double eik_loss  = sum[5] / (double)NG_;
            double sdf_loss  = sum[6] / (double)NG_;
            double con_loss  = (sum[8] > 0.0) ? (sum[7] / sum[8]) : 0.0;

            out[0] = (float)(normal_loss + depth_loss + pc_loss + mask_loss +
                             eik_loss + sdf_loss + con_loss);
        }
    }
}

// ---------------------------------------------------------------------------
// Launch
// ---------------------------------------------------------------------------
extern "C" void kernel_launch(void* const* d_in, const int* in_sizes, int n_in,
                              void* d_out, int out_size) {
    const float* normal_pred = (const float*)d_in[0];
    const float* normal_gt   = (const float*)d_in[1];
    const float* depth_pred  = (const float*)d_in[2];
    const float* depth_gt    = (const float*)d_in[3];
    const float* X           = (const float*)d_in[4];
    const float* Y           = (const float*)d_in[5];
    const float* mask        = (const float*)d_in[6];
    const float* comp_mask   = (const float*)d_in[7];
    const float* gradients   = (const float*)d_in[8];
    const float* sdf         = (const float*)d_in[9];
    const float* nw_all      = (const float*)d_in[10];
    const float* vis_mask    = (const float*)d_in[11];
    const float* weights     = (const float*)d_in[12];
    float* out = (float*)d_out;

    k_fused<<<NBLK, NTH>>>(normal_pred, normal_gt, depth_pred, depth_gt,
                           X, Y, mask, comp_mask, gradients, sdf,
                           nw_all, vis_mask, weights, out);
}